// round 7
// baseline (speedup 1.0000x reference)
#include <cuda_runtime.h>
#include <cstdint>

#define Bsz     32768
#define Dd      1024
#define Cc      40
#define CT      80            // 40 fwd + 40 rev output columns
#define RB      128           // rows (M) per CTA -> 256 CTAs
#define THREADS 256           // 8 warps: 4 M-warps x 2 N-warps, each 2 m-tiles x 5 n-tiles
#define KC      32            // k per chunk (128B per row)
#define NCH     (Dd / KC)     // 32
#define NSTAGE  3
#define PADK    40            // floats/row (160B, 16B-aligned, LDS.64 phase-conflict-free)

#define A_FLOATS   (RB * PADK)            // 5120
#define B_FLOATS   (CT * PADK)            // 3200
#define STAGE_F    (A_FLOATS + B_FLOATS)  // 8320 floats = 33280 B
#define OFF0_F     256                    // 1024 B header (mbarriers)
#define SMEM_BYTES ((OFF0_F + NSTAGE * STAGE_F) * 4)   // 100864 B -> 2 CTAs/SM

#define TXBYTES    ((RB + CT) * 128)      // 26624 B per chunk

// epilogue overlay (aliases stage buffers after mainloop)
#define BROW    81
#define EPI_BASE_F  OFF0_F
#define EPI_WT_F    (EPI_BASE_F + RB * BROW)
#define EPI_BB_F    (EPI_WT_F + 2 * Cc * Cc)

extern __shared__ float smf[];

// pack two fp32 -> f16x2 (lo in low half): PTX first source fills HIGH half
__device__ __forceinline__ uint32_t pk(float lo, float hi) {
    uint32_t r;
    asm("cvt.rn.f16x2.f32 %0, %1, %2;" : "=r"(r) : "f"(hi), "f"(lo));
    return r;
}

__device__ __forceinline__ void mma_16x8x16(float* d, const uint32_t* a,
                                            const uint32_t* bf) {
    asm volatile(
        "mma.sync.aligned.m16n8k16.row.col.f32.f16.f16.f32 "
        "{%0,%1,%2,%3}, {%4,%5,%6,%7}, {%8,%9}, {%0,%1,%2,%3};"
        : "+f"(d[0]), "+f"(d[1]), "+f"(d[2]), "+f"(d[3])
        : "r"(a[0]), "r"(a[1]), "r"(a[2]), "r"(a[3]), "r"(bf[0]), "r"(bf[1]));
}

#define MBAR_INIT(a, n) \
    asm volatile("mbarrier.init.shared.b64 [%0], %1;" :: "r"(a), "r"(n) : "memory")

#define MBAR_EXPECT_TX(a, bytes) \
    asm volatile("mbarrier.arrive.expect_tx.shared.b64 _, [%0], %1;" \
                 :: "r"(a), "r"(bytes) : "memory")

#define MBAR_WAIT(a, par) do {                                              \
    asm volatile(                                                           \
        "{\n\t.reg .pred P1;\n\t"                                           \
        "WL_%=:\n\t"                                                        \
        "mbarrier.try_wait.parity.acquire.cta.shared::cta.b64 P1, [%0], %1, 0x989680;\n\t" \
        "@P1 bra.uni WD_%=;\n\t"                                            \
        "bra.uni WL_%=;\n\t"                                                \
        "WD_%=:\n\t}"                                                       \
        :: "r"(a), "r"(par) : "memory");                                    \
} while (0)

__global__ void __launch_bounds__(THREADS, 2)
bichain_blk(const float* __restrict__ src,
            const float* __restrict__ W,  const float* __restrict__ b,
            const float* __restrict__ Wr, const float* __restrict__ br,
            float* __restrict__ out) {
    const int tid  = threadIdx.x;
    const int warp = tid >> 5;
    const int lane = tid & 31;
    const int row0 = blockIdx.x * RB;

    uint32_t smb;
    asm("{ .reg .u64 t; cvta.to.shared.u64 t, %1; cvt.u32.u64 %0, t; }"
        : "=r"(smb) : "l"(smf));

    // mbarriers: full[s] at byte offset 8 + 8s
    if (tid == 0) {
        #pragma unroll
        for (int s = 0; s < NSTAGE; ++s) MBAR_INIT(smb + 8 + 8 * s, 1);
    }
    __syncthreads();

    // ---- producer state: one 128B bulk row per thread (tid < 208) ----
    const char* myG = nullptr;
    uint32_t    myDoff = 0;            // offset within a stage (bytes)
    if (tid < RB) {
        myG    = (const char*)(src + (size_t)(row0 + tid) * Dd);
        myDoff = (uint32_t)tid * 160u;
    } else if (tid < RB + CT) {
        const int r = tid - RB;
        myG = (const char*)(r < Cc ? W  + (size_t)r        * (Dd + Cc)
                                   : Wr + (size_t)(r - Cc) * (Dd + Cc));
        myDoff = (uint32_t)A_FLOATS * 4u + (uint32_t)r * 160u;
    }

    auto issue = [&](int ch) {
        const int st = ch % NSTAGE;
        const uint32_t mbar = smb + 8 + 8 * st;
        if (tid == 0) MBAR_EXPECT_TX(mbar, TXBYTES);
        if (tid < RB + CT) {
            const uint32_t d = smb + (OFF0_F * 4u) + (uint32_t)st * (STAGE_F * 4u) + myDoff;
            asm volatile(
                "cp.async.bulk.shared::cluster.global.mbarrier::complete_tx::bytes "
                "[%0], [%1], 128, [%2];"
                :: "r"(d), "l"(myG + (size_t)ch * 128), "r"(mbar) : "memory");
        }
    };

    // warp tiling: 4 M-warps (32 rows each) x 2 N-warps (40 cols each)
    const int mw = warp >> 1;
    const int nw = warp & 1;
    const int qr = lane >> 2;
    const int qc = lane & 3;

    int rA2[2][2], rB2[5];
    #pragma unroll
    for (int mt = 0; mt < 2; ++mt) {
        const int r = mw * 32 + mt * 16 + qr;
        rA2[mt][0] = r * (PADK / 2) + qc;
        rA2[mt][1] = (r + 8) * (PADK / 2) + qc;
    }
    #pragma unroll
    for (int t = 0; t < 5; ++t)
        rB2[t] = (nw * 40 + t * 8 + qr) * (PADK / 2) + qc;

    float acc[2][5][4];
    #pragma unroll
    for (int mt = 0; mt < 2; ++mt)
        #pragma unroll
        for (int t = 0; t < 5; ++t)
            #pragma unroll
            for (int e = 0; e < 4; ++e) acc[mt][t][e] = 0.f;

    issue(0); issue(1); issue(2);

    for (int ch = 0; ch < NCH; ++ch) {
        const int st = ch % NSTAGE;
        const int par = (ch / NSTAGE) & 1;
        MBAR_WAIT(smb + 8 + 8 * st, par);

        const float2* Ap2 = (const float2*)(smf + OFF0_F + st * STAGE_F);
        const float2* Bp2 = (const float2*)((const float*)Ap2 + A_FLOATS);

        #pragma unroll
        for (int kk = 0; kk < 2; ++kk) {              // two k16 steps
            const int kb2 = kk * 8;
            uint32_t afr[2][4], bfr[5][2];
            #pragma unroll
            for (int mt = 0; mt < 2; ++mt) {
                float2 p0 = Ap2[rA2[mt][0] + kb2];
                float2 p1 = Ap2[rA2[mt][1] + kb2];
                float2 p2 = Ap2[rA2[mt][0] + kb2 + 4];
                float2 p3 = Ap2[rA2[mt][1] + kb2 + 4];
                afr[mt][0] = pk(p0.x, p0.y);
                afr[mt][1] = pk(p1.x, p1.y);
                afr[mt][2] = pk(p2.x, p2.y);
                afr[mt][3] = pk(p3.x, p3.y);
            }
            #pragma unroll
            for (int t = 0; t < 5; ++t) {
                float2 q0 = Bp2[rB2[t] + kb2];
                float2 q1 = Bp2[rB2[t] + kb2 + 4];
                bfr[t][0] = pk(q0.x, q0.y);
                bfr[t][1] = pk(q1.x, q1.y);
            }
            #pragma unroll
            for (int mt = 0; mt < 2; ++mt)
                #pragma unroll
                for (int t = 0; t < 5; ++t)
                    mma_16x8x16(acc[mt][t], afr[mt], bfr[t]);
        }

        __syncthreads();                              // stage st fully consumed
        if (ch + NSTAGE < NCH) issue(ch + NSTAGE);    // refill freed stage
    }

    // ---- accumulators -> smem bases[128][81] ----
    float* bases = smf + EPI_BASE_F;
    #pragma unroll
    for (int mt = 0; mt < 2; ++mt) {
        const int r = mw * 32 + mt * 16 + qr;
        #pragma unroll
        for (int t = 0; t < 5; ++t) {
            const int c = nw * 40 + t * 8 + qc * 2;
            bases[(r    ) * BROW + c    ] = acc[mt][t][0];
            bases[(r    ) * BROW + c + 1] = acc[mt][t][1];
            bases[(r + 8) * BROW + c    ] = acc[mt][t][2];
            bases[(r + 8) * BROW + c + 1] = acc[mt][t][3];
        }
    }

    // chain tail weights W[:,1024:1064] + biases
    float* wt = smf + EPI_WT_F;
    float* bb = smf + EPI_BB_F;
    for (int idx = tid; idx < 2 * Cc * Cc; idx += THREADS) {
        const int chn = idx / (Cc * Cc);
        const int rem = idx - chn * Cc * Cc;
        const int i = rem / Cc, j = rem % Cc;
        const float* Wp = chn ? Wr : W;
        wt[idx] = Wp[(size_t)i * (Dd + Cc) + Dd + j];
    }
    if (tid < 2 * Cc) bb[tid] = (tid < Cc) ? b[tid] : br[tid - Cc];
    __syncthreads();

    // ---- sequential chains: 256 threads = 128 rows x 2 chains ----
    {
        const int row = tid >> 1, chn = tid & 1;
        float* my        = bases + row * BROW + chn * Cc;
        const float* wtc = wt + chn * Cc * Cc;
        const float* bbc = bb + chn * Cc;
        float s[Cc];
        #pragma unroll
        for (int i = 0; i < Cc; ++i) {
            float x = my[i] + bbc[i];
            #pragma unroll
            for (int j = 0; j < i; ++j)
                x = fmaf(s[j], wtc[i * Cc + j], x);
            s[i] = 1.0f / (1.0f + __expf(-x));
            my[i] = s[i];
        }
    }
    __syncthreads();

    // ---- combine fwd + reversed rev, coalesced store ----
    #pragma unroll
    for (int it = 0; it < (RB * Cc) / THREADS; ++it) {   // 20
        const int idx = tid + it * THREADS;
        const int r = idx / Cc, c = idx - r * Cc;
        const float vf = bases[r * BROW + c];
        const float vr = bases[r * BROW + Cc + (Cc - 1 - c)];
        out[(size_t)(row0 + r) * Cc + c] = 0.5f * (vf + vr);
    }
}

extern "C" void kernel_launch(void* const* d_in, const int* in_sizes, int n_in,
                              void* d_out, int out_size) {
    const float* src = (const float*)d_in[0];
    // d_in[1] = attn_mask (unused)
    const float* W   = (const float*)d_in[2];
    const float* b   = (const float*)d_in[3];
    const float* Wr  = (const float*)d_in[4];
    const float* br  = (const float*)d_in[5];
    float* out = (float*)d_out;

    cudaFuncSetAttribute(bichain_blk,
                         cudaFuncAttributeMaxDynamicSharedMemorySize, SMEM_BYTES);
    bichain_blk<<<Bsz / RB, THREADS, SMEM_BYTES>>>(src, W, b, Wr, br, out);
}